// round 3
// baseline (speedup 1.0000x reference)
#include <cuda_runtime.h>
#include <cstdint>

#define B_SZ   1024
#define IN_SZ  128
#define OUT_SZ 10000
#define KCEN   16
#define NT     79              // 79 n-tiles of 128 = 10112 >= 10000
#define MT     8               // 8 m-tiles of 128
#define SSC    64.0f
#define LDT    144             // smem pitch (bytes) for 128B rows -> conflict-free ldmatrix

// ---------------- device scratch ----------------
__device__ uint4  g_wimg[(size_t)NT*KCEN*1024];     // 20.7 MB int8 images (16KB/tile) [n][k]
__device__ uint4  g_ximg[MT*1024];                  // 128 KB int8 images [m][k]
__device__ float  g_sw[(size_t)NT*KCEN*128];        // per (n-tile, kc, col) dequant scale
__device__ float  g_sx[B_SZ];                       // per-row dequant scale
__device__ float  g_xnf[B_SZ*IN_SZ];                // exact normalized x (fp32)
__device__ float  g_clab[B_SZ*KCEN];                // exact label-column cos per kc
__device__ float2 g_part[(size_t)B_SZ*NT];          // per (row, n-tile) (max, sumexp) non-label
__device__ float  g_cosfa[B_SZ], g_sinfa[B_SZ], g_costhr[B_SZ];
__device__ float  g_loss[B_SZ], g_corr[B_SZ];

// ---------------- helpers ----------------
__device__ __forceinline__ uint32_t smem_u32(const void* p) {
    uint32_t a;
    asm("{ .reg .u64 t; cvta.to.shared.u64 t, %1; cvt.u32.u64 %0, t; }" : "=r"(a) : "l"(p));
    return a;
}
__device__ __forceinline__ void cp_async16(uint32_t saddr, const void* gptr) {
    asm volatile("cp.async.cg.shared.global [%0], [%1], 16;\n" :: "r"(saddr), "l"(gptr));
}
#define CP_COMMIT() asm volatile("cp.async.commit_group;\n")

#define LDSM_X4(r0,r1,r2,r3,addr) \
    asm volatile("ldmatrix.sync.aligned.m8n8.x4.shared.b16 {%0,%1,%2,%3}, [%4];" \
        : "=r"(r0),"=r"(r1),"=r"(r2),"=r"(r3) : "r"(addr))

#define IMMA(c0,c1,c2,c3,a0,a1,a2,a3,b0,b1) \
    asm volatile("mma.sync.aligned.m16n8k32.row.col.s32.s8.s8.s32 " \
        "{%0,%1,%2,%3},{%4,%5,%6,%7},{%8,%9},{%0,%1,%2,%3};" \
        : "+r"(c0),"+r"(c1),"+r"(c2),"+r"(c3) \
        : "r"(a0),"r"(a1),"r"(a2),"r"(a3),"r"(b0),"r"(b1))

// ---------------- prep_x: norms, int8 quant, exact xn, margin consts --------
__global__ void prep_x_kernel(const float* __restrict__ x,
                              const float* __restrict__ factor) {
    int b = blockIdx.x, f = threadIdx.x;        // 128 threads
    float v = x[b*IN_SZ + f];
    float s = v*v, a = fabsf(v);
    #pragma unroll
    for (int o = 16; o; o >>= 1) {
        s += __shfl_xor_sync(0xffffffffu, s, o);
        a = fmaxf(a, __shfl_xor_sync(0xffffffffu, a, o));
    }
    __shared__ float ws[4], wa[4];
    if ((f & 31) == 0) { ws[f >> 5] = s; wa[f >> 5] = a; }
    __syncthreads();
    float tot = ws[0] + ws[1] + ws[2] + ws[3];
    float mab = fmaxf(fmaxf(wa[0], wa[1]), fmaxf(wa[2], wa[3]));
    float rinv = 1.f / fmaxf(sqrtf(tot), 1e-12f);
    float qsc = (mab > 0.f) ? 127.f / mab : 0.f;
    int q = __float2int_rn(v * qsc);
    ((char*)g_ximg)[(b >> 7)*16384 + (b & 127)*128 + f] = (char)q;
    g_xnf[b*IN_SZ + f] = v * rinv;
    if (f == 0) {
        g_sx[b] = mab * rinv * (1.f/127.f);
        float fa = powf(1.5f, factor[b] * (1.f/12.f)) * 0.5f;
        float cfa = cosf(fa);
        g_cosfa[b] = cfa; g_sinfa[b] = sinf(fa); g_costhr[b] = -cfa;
    }
}

// ---------------- prep_w: one-pass normalize+quantize+scales+label dots -----
__global__ void prep_w_kernel(const float* __restrict__ w,
                              const int* __restrict__ label) {
    extern __shared__ float tile[];             // 128 x 129 fp32
    __shared__ float sums[256], maxs[256];
    __shared__ float rn[128], qsc[128];
    int kc = blockIdx.x, nt = blockIdx.y, t = threadIdx.x;   // 256 threads
    const float* wk = w + (size_t)kc * IN_SZ * OUT_SZ;
    int o0 = nt * 128;

    #pragma unroll 4
    for (int i = 0; i < 64; i++) {
        int idx = i*256 + t;
        int f = idx >> 7, ol = idx & 127, o = o0 + ol;
        tile[f*129 + ol] = (o < OUT_SZ) ? wk[(size_t)f*OUT_SZ + o] : 0.f;
    }
    __syncthreads();
    {
        int ol = t & 127, half = t >> 7;
        float ss = 0.f, ma = 0.f;
        #pragma unroll 8
        for (int f = half*64; f < half*64 + 64; f++) {
            float v = tile[f*129 + ol]; ss += v*v; ma = fmaxf(ma, fabsf(v));
        }
        sums[t] = ss; maxs[t] = ma;
    }
    __syncthreads();
    if (t < 128) {
        float nrm = sqrtf(sums[t] + sums[t+128]);
        float ma  = fmaxf(maxs[t], maxs[t+128]);
        float rinv = 1.f / fmaxf(nrm, 1e-12f);
        rn[t]  = rinv;
        qsc[t] = (ma > 0.f) ? 127.f / ma : 0.f;
        g_sw[((size_t)nt*KCEN + kc)*128 + t] = (ma > 0.f) ? ma * rinv * (1.f/127.f) : 0.f;
    }
    __syncthreads();

    // exact label-column dots (rare matches; ~13 per block)
    for (int j = t; j < B_SZ; j += 256) {
        int ll = label[j] - o0;
        if (ll >= 0 && ll < 128) {
            const float* xr = g_xnf + j*IN_SZ;
            float d = 0.f;
            #pragma unroll 8
            for (int f = 0; f < IN_SZ; f++) d += xr[f] * tile[f*129 + ll];
            g_clab[j*KCEN + kc] = d * rn[ll];
        }
    }

    // quantize & write int8 image [n=ol][k=f]
    int ol = t & 127, half = t >> 7;
    float q = qsc[ol];
    char* dst = (char*)g_wimg + ((size_t)nt*KCEN + kc)*16384 + ol*128 + half*64;
    #pragma unroll
    for (int cc = 0; cc < 4; cc++) {
        __align__(16) char tmp[16];
        #pragma unroll
        for (int i = 0; i < 16; i++)
            tmp[i] = (char)__float2int_rn(tile[(half*64 + cc*16 + i)*129 + ol] * q);
        *(uint4*)(dst + cc*16) = *(const uint4*)tmp;
    }
}

// ---------------- fused int8 GEMM + max over kc + online softmax partials ---
__global__ void __launch_bounds__(256) gemm_kernel(const int* __restrict__ label) {
    extern __shared__ char sm[];
    __shared__ float sm_m[128], sm_s[128];

    uint32_t sbase = smem_u32(sm);
    uint32_t sA = sbase;
    uint32_t sB = sbase + 128*LDT;              // 2 B buffers
    float* swp = (float*)(sm + 3*128*LDT);      // 16 x 128 scales
    uint32_t ssw = sbase + 3*128*LDT;

    int tid = threadIdx.x, w = tid >> 5, lane = tid & 31;
    int mtile = blockIdx.x, nt = blockIdx.y;
    int wm = w & 3, wn = w >> 2;

    const char* ximg = (const char*)g_ximg + mtile*16384;
    const char* wimg = (const char*)g_wimg + (size_t)nt*KCEN*16384;

    // prologue: A + sw + B0
    #pragma unroll
    for (int i = 0; i < 4; i++) {
        int ci = i*256 + tid;
        cp_async16(sA + (ci >> 3)*LDT + (ci & 7)*16, ximg + ci*16);
    }
    #pragma unroll
    for (int i = 0; i < 2; i++) {
        int ci = i*256 + tid;
        cp_async16(ssw + ci*16, (const char*)(g_sw + (size_t)nt*KCEN*128) + ci*16);
    }
    #pragma unroll
    for (int i = 0; i < 4; i++) {
        int ci = i*256 + tid;
        cp_async16(sB + (ci >> 3)*LDT + (ci & 7)*16, wimg + ci*16);
    }
    CP_COMMIT();

    float mx[2][8][4];
    #pragma unroll
    for (int i = 0; i < 2; i++)
        #pragma unroll
        for (int j = 0; j < 8; j++)
            #pragma unroll
            for (int c = 0; c < 4; c++) mx[i][j][c] = -3.0e38f;

    for (int kc = 0; kc < KCEN; kc++) {
        uint32_t bbuf = sB + (kc & 1)*(128*LDT);
        if (kc + 1 < KCEN) {
            const char* src = wimg + (size_t)(kc + 1)*16384;
            uint32_t dst = sB + ((kc + 1) & 1)*(128*LDT);
            #pragma unroll
            for (int i = 0; i < 4; i++) {
                int ci = i*256 + tid;
                cp_async16(dst + (ci >> 3)*LDT + (ci & 7)*16, src + ci*16);
            }
            CP_COMMIT();
            asm volatile("cp.async.wait_group 1;");
        } else {
            asm volatile("cp.async.wait_group 0;");
        }
        __syncthreads();

        int acc[2][8][4];
        #pragma unroll
        for (int i = 0; i < 2; i++)
            #pragma unroll
            for (int j = 0; j < 8; j++)
                #pragma unroll
                for (int c = 0; c < 4; c++) acc[i][j][c] = 0;

        #pragma unroll
        for (int ks = 0; ks < 4; ks++) {
            int kb = ks * 32;
            uint32_t a[2][4];
            #pragma unroll
            for (int mt = 0; mt < 2; mt++) {
                uint32_t addr = sA + (uint32_t)((wm*32 + mt*16 + (lane & 7)
                              + ((lane >> 3) & 1)*8)*LDT + kb + (lane >> 4)*16);
                LDSM_X4(a[mt][0], a[mt][1], a[mt][2], a[mt][3], addr);
            }
            uint32_t q[4][4];
            #pragma unroll
            for (int p = 0; p < 4; p++) {
                uint32_t addr = bbuf + (uint32_t)((wn*64 + p*16 + (lane & 7)
                              + (lane >> 4)*8)*LDT + kb + ((lane >> 3) & 1)*16);
                LDSM_X4(q[p][0], q[p][1], q[p][2], q[p][3], addr);
            }
            #pragma unroll
            for (int mt = 0; mt < 2; mt++)
                #pragma unroll
                for (int nf = 0; nf < 8; nf++)
                    IMMA(acc[mt][nf][0], acc[mt][nf][1], acc[mt][nf][2], acc[mt][nf][3],
                         a[mt][0], a[mt][1], a[mt][2], a[mt][3],
                         q[nf >> 1][(nf & 1)*2], q[nf >> 1][(nf & 1)*2 + 1]);
        }
        __syncthreads();

        // fold: max over kc with per-(kc,col) weight scale (row scale applied later)
        const float* swk = swp + kc*128;
        #pragma unroll
        for (int nf = 0; nf < 8; nf++) {
            float s0 = swk[wn*64 + nf*8 + (lane & 3)*2];
            float s1 = swk[wn*64 + nf*8 + (lane & 3)*2 + 1];
            #pragma unroll
            for (int mt = 0; mt < 2; mt++) {
                mx[mt][nf][0] = fmaxf(mx[mt][nf][0], __int2float_rn(acc[mt][nf][0]) * s0);
                mx[mt][nf][1] = fmaxf(mx[mt][nf][1], __int2float_rn(acc[mt][nf][1]) * s1);
                mx[mt][nf][2] = fmaxf(mx[mt][nf][2], __int2float_rn(acc[mt][nf][2]) * s0);
                mx[mt][nf][3] = fmaxf(mx[mt][nf][3], __int2float_rn(acc[mt][nf][3]) * s1);
            }
        }
    }

    // ---- fused epilogue: 4 row-states per thread, 16 cols each ----
    int rbase = mtile*128 + wm*32 + (lane >> 2);
    float sxv[4]; int labv[4];
    #pragma unroll
    for (int st = 0; st < 4; st++) {
        int r = rbase + (st >> 1)*16 + (st & 1)*8;
        sxv[st] = g_sx[r];
        labv[st] = label[r];
    }
    float m4[4] = {-3.0e38f, -3.0e38f, -3.0e38f, -3.0e38f};
    float s4[4] = {0.f, 0.f, 0.f, 0.f};
    int colb = nt*128 + wn*64;

    #pragma unroll
    for (int nf = 0; nf < 8; nf++)
        #pragma unroll
        for (int c = 0; c < 4; c++) {
            int col = colb + nf*8 + (lane & 3)*2 + (c & 1);
            #pragma unroll
            for (int mt = 0; mt < 2; mt++) {
                int st = mt*2 + (c >> 1);
                if (col < OUT_SZ && col != labv[st]) {
                    float cv = mx[mt][nf][c] * sxv[st];
                    cv = fminf(fmaxf(cv, -1.0f + 1e-6f), 1.0f - 1e-6f);
                    float l = cv * SSC;
                    if (l > m4[st]) { s4[st] = s4[st]*__expf(m4[st] - l) + 1.f; m4[st] = l; }
                    else            { s4[st] += __expf(l - m4[st]); }
                }
            }
        }

    // merge across the 4 lanes sharing rows (lane^1, lane^2)
    #pragma unroll
    for (int o = 1; o <= 2; o <<= 1) {
        #pragma unroll
        for (int st = 0; st < 4; st++) {
            float mo = __shfl_xor_sync(0xffffffffu, m4[st], o);
            float so = __shfl_xor_sync(0xffffffffu, s4[st], o);
            float M = fmaxf(m4[st], mo);
            s4[st] = s4[st]*__expf(m4[st] - M) + so*__expf(mo - M);
            m4[st] = M;
        }
    }
    // merge across the two column-half warps (wn=0 writes, wn=1 combines)
    if (wn == 0 && (lane & 3) == 0) {
        #pragma unroll
        for (int st = 0; st < 4; st++) {
            int rl = wm*32 + (lane >> 2) + (st >> 1)*16 + (st & 1)*8;
            sm_m[rl] = m4[st]; sm_s[rl] = s4[st];
        }
    }
    __syncthreads();
    if (wn == 1 && (lane & 3) == 0) {
        #pragma unroll
        for (int st = 0; st < 4; st++) {
            int rl = wm*32 + (lane >> 2) + (st >> 1)*16 + (st & 1)*8;
            float mo = sm_m[rl], so = sm_s[rl];
            float M = fmaxf(m4[st], mo);
            float S = s4[st]*__expf(m4[st] - M) + so*__expf(mo - M);
            g_part[(size_t)(mtile*128 + rl)*NT + nt] = make_float2(M, S);
        }
    }
}

// ---------------- combine n-tile partials + exact label logit per row -------
__global__ void rowcombine_kernel(const int* __restrict__ label) {
    int r = blockIdx.x, t = threadIdx.x;        // 128 threads
    float m = -3.0e38f, s = 0.f;
    if (t < NT) { float2 p = g_part[(size_t)r*NT + t]; m = p.x; s = p.y; }
    __shared__ float rm[128], rs[128];
    rm[t] = m; rs[t] = s;
    __syncthreads();
    for (int st = 64; st; st >>= 1) {
        if (t < st) {
            float m1 = rm[t], m2 = rm[t+st];
            float M = fmaxf(m1, m2);
            rs[t] = rs[t]*__expf(m1 - M) + rs[t+st]*__expf(m2 - M);
            rm[t] = M;
        }
        __syncthreads();
    }
    if (t == 0) {
        float c = -2.f;
        #pragma unroll
        for (int k = 0; k < KCEN; k++) c = fmaxf(c, g_clab[r*KCEN + k]);
        c = fminf(fmaxf(c, -1.0f + 1e-6f), 1.0f - 1e-6f);
        float l;
        if (c >= g_costhr[r])
            l = (c * g_cosfa[r] - sqrtf(fmaxf(1.f - c*c, 0.f)) * g_sinfa[r]) * SSC;
        else
            l = c * SSC;
        float Mn = rm[0], Sn = rs[0];
        float M = fmaxf(Mn, l);
        float S = Sn*__expf(Mn - M) + __expf(l - M);
        g_loss[r] = logf(S) + M - l;
        g_corr[r] = (l > Mn) ? 1.f : 0.f;
        (void)label;
    }
}

// ---------------- final reduction ---------------------------------------------
__global__ void fin_kernel(float* __restrict__ out) {
    int t = threadIdx.x;                        // 1024 threads
    __shared__ float sl[1024], sc[1024];
    sl[t] = g_loss[t]; sc[t] = g_corr[t];
    __syncthreads();
    for (int st = 512; st; st >>= 1) {
        if (t < st) { sl[t] += sl[t+st]; sc[t] += sc[t+st]; }
        __syncthreads();
    }
    if (t == 0) {
        out[0] = sl[0] * (1.f/1024.f);
        out[1] = sc[0] * (100.f/1024.f);
    }
}

// ---------------- launch --------------------------------------------------------
extern "C" void kernel_launch(void* const* d_in, const int* in_sizes, int n_in,
                              void* d_out, int out_size) {
    const float* x      = (const float*)d_in[0];
    const float* factor = (const float*)d_in[1];
    const int*   label  = (const int*)  d_in[2];
    const float* w      = (const float*)d_in[3];
    float* out = (float*)d_out;

    int gemm_smem = 3*128*LDT + KCEN*128*4;     // 55296 + 8192 = 63488
    cudaFuncSetAttribute(prep_w_kernel, cudaFuncAttributeMaxDynamicSharedMemorySize, 128*129*4);
    cudaFuncSetAttribute(gemm_kernel,   cudaFuncAttributeMaxDynamicSharedMemorySize, gemm_smem);

    prep_x_kernel<<<B_SZ, 128>>>(x, factor);
    prep_w_kernel<<<dim3(KCEN, NT), 256, 128*129*4>>>(w, label);
    gemm_kernel<<<dim3(MT, NT), 256, gemm_smem>>>(label);
    rowcombine_kernel<<<B_SZ, 128>>>(label);
    fin_kernel<<<1, 1024>>>(out);
}

// round 4
// speedup vs baseline: 1.8726x; 1.8726x over previous
#include <cuda_runtime.h>
#include <cuda_fp16.h>
#include <cstdint>

#define B_SZ   1024
#define IN_SZ  128
#define OUT_SZ 10000
#define KCEN   16
#define NT     79              // 79 n-tiles of 128 = 10112 >= 10000
#define MT     8               // 8 m-tiles of 128
#define SSC    64.0f
#define LDH    136             // smem pitch in halves (272B) -> conflict-free ldmatrix
#define TILEB  34816           // 128 * 272 bytes per smem tile

// ---------------- device scratch ----------------
__device__ uint4  g_wimg[(size_t)NT*KCEN*2048];     // 41.4 MB fp16 images [n][k], 32KB/tile
__device__ uint4  g_ximg[MT*2048];                  // 256 KB fp16 images [m][k]
__device__ float  g_xnf[B_SZ*IN_SZ];                // exact normalized x (fp32)
__device__ float  g_clab[B_SZ*KCEN];                // exact label-column cos per kc
__device__ float2 g_part[(size_t)B_SZ*NT];          // per (row, n-tile) (max, sumexp) non-label
__device__ float  g_cosfa[B_SZ], g_sinfa[B_SZ], g_costhr[B_SZ];
__device__ float  g_loss[B_SZ], g_corr[B_SZ];

// ---------------- helpers ----------------
__device__ __forceinline__ uint32_t smem_u32(const void* p) {
    uint32_t a;
    asm("{ .reg .u64 t; cvta.to.shared.u64 t, %1; cvt.u32.u64 %0, t; }" : "=r"(a) : "l"(p));
    return a;
}
__device__ __forceinline__ void cp_async16(uint32_t saddr, const void* gptr) {
    asm volatile("cp.async.cg.shared.global [%0], [%1], 16;\n" :: "r"(saddr), "l"(gptr));
}
#define CP_COMMIT() asm volatile("cp.async.commit_group;\n")

#define LDSM_X4(r0,r1,r2,r3,addr) \
    asm volatile("ldmatrix.sync.aligned.m8n8.x4.shared.b16 {%0,%1,%2,%3}, [%4];" \
        : "=r"(r0),"=r"(r1),"=r"(r2),"=r"(r3) : "r"(addr))

#define MMA16816(c0,c1,c2,c3,a0,a1,a2,a3,b0,b1) \
    asm volatile("mma.sync.aligned.m16n8k16.row.col.f32.f16.f16.f32 " \
        "{%0,%1,%2,%3},{%4,%5,%6,%7},{%8,%9},{%0,%1,%2,%3};" \
        : "+f"(c0),"+f"(c1),"+f"(c2),"+f"(c3) \
        : "r"(a0),"r"(a1),"r"(a2),"r"(a3),"r"(b0),"r"(b1))

// ---------------- prep_x: normalize rows -> fp16 [m][k] + exact xn + consts
__global__ void prep_x_kernel(const float* __restrict__ x,
                              const float* __restrict__ factor) {
    int b = blockIdx.x, f = threadIdx.x;        // 128 threads
    float v = x[b*IN_SZ + f];
    float s = v*v;
    #pragma unroll
    for (int o = 16; o; o >>= 1) s += __shfl_xor_sync(0xffffffffu, s, o);
    __shared__ float ws[4];
    if ((f & 31) == 0) ws[f >> 5] = s;
    __syncthreads();
    float tot = ws[0] + ws[1] + ws[2] + ws[3];
    float rinv = 1.f / fmaxf(sqrtf(tot), 1e-12f);
    float xn = v * rinv;
    ((__half*)g_ximg)[(b >> 7)*16384 + (b & 127)*128 + f] = __float2half(xn);
    g_xnf[b*IN_SZ + f] = xn;
    if (f == 0) {
        float fa = powf(1.5f, factor[b] * (1.f/12.f)) * 0.5f;
        float cfa = cosf(fa);
        g_cosfa[b] = cfa; g_sinfa[b] = sinf(fa); g_costhr[b] = -cfa;
    }
}

// ---------------- prep_w: one-pass normalize -> fp16 [n][k] + exact label dots
__global__ void prep_w_kernel(const float* __restrict__ w,
                              const int* __restrict__ label) {
    extern __shared__ float tile[];             // 128 x 129 fp32
    __shared__ float sums[256];
    __shared__ float rn[128];
    int kc = blockIdx.x, nt = blockIdx.y, t = threadIdx.x;   // 256 threads
    const float* wk = w + (size_t)kc * IN_SZ * OUT_SZ;
    int o0 = nt * 128;

    #pragma unroll 4
    for (int i = 0; i < 64; i++) {
        int idx = i*256 + t;
        int f = idx >> 7, ol = idx & 127, o = o0 + ol;
        tile[f*129 + ol] = (o < OUT_SZ) ? wk[(size_t)f*OUT_SZ + o] : 0.f;
    }
    __syncthreads();
    {
        int ol = t & 127, half = t >> 7;
        float ss = 0.f;
        #pragma unroll 8
        for (int f = half*64; f < half*64 + 64; f++) { float v = tile[f*129 + ol]; ss += v*v; }
        sums[t] = ss;
    }
    __syncthreads();
    if (t < 128)
        rn[t] = 1.f / fmaxf(sqrtf(sums[t] + sums[t+128]), 1e-12f);
    __syncthreads();

    // exact label-column cos (rare matches; ~13 per block)
    for (int j = t; j < B_SZ; j += 256) {
        int ll = label[j] - o0;
        if (ll >= 0 && ll < 128) {
            const float* xr = g_xnf + j*IN_SZ;
            float d = 0.f;
            #pragma unroll 8
            for (int f = 0; f < IN_SZ; f++) d += xr[f] * tile[f*129 + ll];
            g_clab[j*KCEN + kc] = d * rn[ll];
        }
    }

    // coalesced fp16 [n][k] write: chunk ci -> row=ci>>4 (n), kchunk=ci&15
    char* img = (char*)g_wimg + ((size_t)nt*KCEN + kc)*32768;
    #pragma unroll
    for (int i = 0; i < 8; i++) {
        int ci = i*256 + t;
        int row = ci >> 4, kch = ci & 15;
        float rv = rn[row];
        __align__(16) __half hs[8];
        #pragma unroll
        for (int j = 0; j < 8; j++)
            hs[j] = __float2half(tile[(kch*8 + j)*129 + row] * rv);
        *(uint4*)(img + row*256 + kch*16) = *(const uint4*)hs;
    }
}

// ---------------- fused fp16 GEMM + max over kc + online softmax partials ---
__global__ void __launch_bounds__(256, 1) gemm_kernel(const int* __restrict__ label) {
    extern __shared__ char sm[];
    __shared__ float sm_m[128], sm_s[128];

    uint32_t sbase = smem_u32(sm);
    uint32_t sA = sbase;
    uint32_t sB = sbase + TILEB;                // 3 B buffers

    int tid = threadIdx.x, w = tid >> 5, lane = tid & 31;
    int mtile = blockIdx.x, nt = blockIdx.y;
    int wm = w & 3, wn = w >> 2;

    const char* ximg = (const char*)g_ximg + mtile*32768;
    const char* wimg = (const char*)g_wimg + (size_t)nt*KCEN*32768;

    // prologue: G(A+B0), G(B1)
    #pragma unroll
    for (int i = 0; i < 8; i++) {
        int ci = i*256 + tid;
        cp_async16(sA + (ci >> 4)*272 + (ci & 15)*16, ximg + ci*16);
    }
    #pragma unroll
    for (int i = 0; i < 8; i++) {
        int ci = i*256 + tid;
        cp_async16(sB + (ci >> 4)*272 + (ci & 15)*16, wimg + ci*16);
    }
    CP_COMMIT();
    #pragma unroll
    for (int i = 0; i < 8; i++) {
        int ci = i*256 + tid;
        cp_async16(sB + TILEB + (ci >> 4)*272 + (ci & 15)*16, wimg + 32768 + ci*16);
    }
    CP_COMMIT();

    // ldmatrix base addresses
    uint32_t aA = sA + (uint32_t)((wm*32 + (lane & 15))*272 + (lane >> 4)*16);
    uint32_t aBoff = (uint32_t)((wn*64 + (lane >> 4)*8 + (lane & 7))*272
                   + ((lane >> 3) & 1)*16);

    float mx[2][8][4];
    #pragma unroll
    for (int i = 0; i < 2; i++)
        #pragma unroll
        for (int j = 0; j < 8; j++)
            #pragma unroll
            for (int c = 0; c < 4; c++) mx[i][j][c] = -3.0e38f;

    for (int kc = 0; kc < KCEN; kc++) {
        if (kc < 15) asm volatile("cp.async.wait_group 1;");
        else         asm volatile("cp.async.wait_group 0;");
        __syncthreads();

        // prefetch kc+2
        if (kc + 2 < KCEN) {
            const char* src = wimg + (size_t)(kc + 2)*32768;
            uint32_t dst = sB + ((kc + 2) % 3)*TILEB;
            #pragma unroll
            for (int i = 0; i < 8; i++) {
                int ci = i*256 + tid;
                cp_async16(dst + (ci >> 4)*272 + (ci & 15)*16, src + ci*16);
            }
            CP_COMMIT();
        }

        uint32_t bbuf = sB + (kc % 3)*TILEB;
        float acc[2][8][4];
        #pragma unroll
        for (int i = 0; i < 2; i++)
            #pragma unroll
            for (int j = 0; j < 8; j++)
                #pragma unroll
                for (int c = 0; c < 4; c++) acc[i][j][c] = 0.f;

        #pragma unroll
        for (int ks = 0; ks < 8; ks++) {
            uint32_t a[2][4];
            #pragma unroll
            for (int mt = 0; mt < 2; mt++)
                LDSM_X4(a[mt][0], a[mt][1], a[mt][2], a[mt][3],
                        aA + mt*16*272 + ks*32);
            uint32_t bq[4][4];
            #pragma unroll
            for (int p = 0; p < 4; p++)
                LDSM_X4(bq[p][0], bq[p][1], bq[p][2], bq[p][3],
                        bbuf + aBoff + p*16*272 + ks*32);
            #pragma unroll
            for (int mt = 0; mt < 2; mt++)
                #pragma unroll
                for (int nf = 0; nf < 8; nf++)
                    MMA16816(acc[mt][nf][0], acc[mt][nf][1], acc[mt][nf][2], acc[mt][nf][3],
                             a[mt][0], a[mt][1], a[mt][2], a[mt][3],
                             bq[nf >> 1][(nf & 1)*2], bq[nf >> 1][(nf & 1)*2 + 1]);
        }
        #pragma unroll
        for (int i = 0; i < 2; i++)
            #pragma unroll
            for (int j = 0; j < 8; j++)
                #pragma unroll
                for (int c = 0; c < 4; c++)
                    mx[i][j][c] = fmaxf(mx[i][j][c], acc[i][j][c]);
    }

    // ---- fused epilogue: 4 row-states per thread, 16 cols each ----
    int rbase = mtile*128 + wm*32 + (lane >> 2);
    int labv[4];
    #pragma unroll
    for (int st = 0; st < 4; st++)
        labv[st] = label[rbase + (st >> 1)*16 + (st & 1)*8];

    float m4[4] = {-3.0e38f, -3.0e38f, -3.0e38f, -3.0e38f};
    float s4[4] = {0.f, 0.f, 0.f, 0.f};
    int colb = nt*128 + wn*64;

    #pragma unroll
    for (int nf = 0; nf < 8; nf++)
        #pragma unroll
        for (int c = 0; c < 4; c++) {
            int col = colb + nf*8 + (lane & 3)*2 + (c & 1);
            #pragma unroll
            for (int mt = 0; mt < 2; mt++) {
                int st = mt*2 + (c >> 1);
                if (col < OUT_SZ && col != labv[st]) {
                    float cv = mx[mt][nf][c];
                    cv = fminf(fmaxf(cv, -1.0f + 1e-6f), 1.0f - 1e-6f);
                    float l = cv * SSC;
                    if (l > m4[st]) { s4[st] = s4[st]*__expf(m4[st] - l) + 1.f; m4[st] = l; }
                    else            { s4[st] += __expf(l - m4[st]); }
                }
            }
        }

    // merge the 4 lanes of each row-quad
    #pragma unroll
    for (int o = 1; o <= 2; o <<= 1) {
        #pragma unroll
        for (int st = 0; st < 4; st++) {
            float mo = __shfl_xor_sync(0xffffffffu, m4[st], o);
            float so = __shfl_xor_sync(0xffffffffu, s4[st], o);
            float M = fmaxf(m4[st], mo);
            s4[st] = s4[st]*__expf(m4[st] - M) + so*__expf(mo - M);
            m4[st] = M;
        }
    }
    __syncthreads();
    // merge the two column-half warps
    if (wn == 0 && (lane & 3) == 0) {
        #pragma unroll
        for (int st = 0; st < 4; st++) {
            int rl = wm*32 + (lane >> 2) + (st >> 1)*16 + (st & 1)*8;
            sm_m[rl] = m4[st]; sm_s[rl] = s4[st];
        }
    }
    __syncthreads();
    if (wn == 1 && (lane & 3) == 0) {
        #pragma unroll
        for (int st = 0; st < 4; st++) {
            int rl = wm*32 + (lane >> 2) + (st >> 1)*16 + (st & 1)*8;
            float mo = sm_m[rl], so = sm_s[rl];
            float M = fmaxf(m4[st], mo);
            float S = s4[st]*__expf(m4[st] - M) + so*__expf(mo - M);
            g_part[(size_t)(mtile*128 + rl)*NT + nt] = make_float2(M, S);
        }
    }
}

// ---------------- combine n-tile partials + exact label logit per row -------
__global__ void rowcombine_kernel(const int* __restrict__ label) {
    int r = blockIdx.x, t = threadIdx.x;        // 128 threads
    float m = -3.0e38f, s = 0.f;
    if (t < NT) { float2 p = g_part[(size_t)r*NT + t]; m = p.x; s = p.y; }
    __shared__ float rm[128], rs[128];
    rm[t] = m; rs[t] = s;
    __syncthreads();
    for (int st = 64; st; st >>= 1) {
        if (t < st) {
            float m1 = rm[t], m2 = rm[t+st];
            float M = fmaxf(m1, m2);
            rs[t] = rs[t]*__expf(m1 - M) + rs[t+st]*__expf(m2 - M);
            rm[t] = M;
        }
        __syncthreads();
    }
    if (t == 0) {
        float c = -2.f;
        #pragma unroll
        for (int k = 0; k < KCEN; k++) c = fmaxf(c, g_clab[r*KCEN + k]);
        c = fminf(fmaxf(c, -1.0f + 1e-6f), 1.0f - 1e-6f);
        float l;
        if (c >= g_costhr[r])
            l = (c * g_cosfa[r] - sqrtf(fmaxf(1.f - c*c, 0.f)) * g_sinfa[r]) * SSC;
        else
            l = c * SSC;
        float Mn = rm[0], Sn = rs[0];
        float M = fmaxf(Mn, l);
        float S = Sn*__expf(Mn - M) + __expf(l - M);
        g_loss[r] = logf(S) + M - l;
        g_corr[r] = (l > Mn) ? 1.f : 0.f;
        (void)label;
    }
}

// ---------------- final reduction ---------------------------------------------
__global__ void fin_kernel(float* __restrict__ out) {
    int t = threadIdx.x;                        // 1024 threads
    __shared__ float sl[1024], sc[1024];
    sl[t] = g_loss[t]; sc[t] = g_corr[t];
    __syncthreads();
    for (int st = 512; st; st >>= 1) {
        if (t < st) { sl[t] += sl[t+st]; sc[t] += sc[t+st]; }
        __syncthreads();
    }
    if (t == 0) {
        out[0] = sl[0] * (1.f/1024.f);
        out[1] = sc[0] * (100.f/1024.f);
    }
}

// ---------------- launch --------------------------------------------------------
extern "C" void kernel_launch(void* const* d_in, const int* in_sizes, int n_in,
                              void* d_out, int out_size) {
    const float* x      = (const float*)d_in[0];
    const float* factor = (const float*)d_in[1];
    const int*   label  = (const int*)  d_in[2];
    const float* w      = (const float*)d_in[3];
    float* out = (float*)d_out;

    int gemm_smem = 4*TILEB;                    // 139264
    cudaFuncSetAttribute(prep_w_kernel, cudaFuncAttributeMaxDynamicSharedMemorySize, 128*129*4);
    cudaFuncSetAttribute(gemm_kernel,   cudaFuncAttributeMaxDynamicSharedMemorySize, gemm_smem);

    prep_x_kernel<<<B_SZ, 128>>>(x, factor);
    prep_w_kernel<<<dim3(KCEN, NT), 256, 128*129*4>>>(w, label);
    gemm_kernel<<<dim3(MT, NT), 256, gemm_smem>>>(label);
    rowcombine_kernel<<<B_SZ, 128>>>(label);
    fin_kernel<<<1, 1024>>>(out);
}